// round 16
// baseline (speedup 1.0000x reference)
#include <cuda_runtime.h>
#include <cuda_bf16.h>
#include <cuda_fp16.h>
#include <cstdint>

// Problem constants
#define B_    4
#define H_    1024
#define L_    4096
#define N2L   8192        // 2L (kernel length)
#define NBL   (B_*L_)     // 16384  (GEMM N)
#define KDIM  1024        // GEMM K  (= H)
#define MDIM  2048        // GEMM M  (= 2H, packed a/g rows)
#define LAM   0.1f

// ---------------- scratch (static __device__) ----------------
__device__ int      g_nnz[H_];
__device__ int      g_tpos[H_ * N2L];
__device__ float    g_tval[H_ * N2L];
__device__ __half   g_yh[(size_t)NBL * KDIM];
__device__ __half   g_wh[(size_t)MDIM * KDIM];
__device__ float    g_bpack[MDIM];

// ---------------- helpers ----------------
__device__ __forceinline__ uint32_t smem_u32(const void* p) {
    uint32_t a;
    asm("{ .reg .u64 t; cvta.to.shared.u64 t, %1; cvt.u32.u64 %0, t; }" : "=r"(a) : "l"(p));
    return a;
}
#define SWZ(o) ((o) ^ (((o) >> 3) & 0x70))

__device__ __forceinline__ void cpa16(uint32_t s, const void* g) {
    asm volatile("cp.async.cg.shared.global [%0], [%1], 16;"
                 :: "r"(s), "l"(__cvta_generic_to_global(g)));
}
__device__ __forceinline__ void cpa_commit() { asm volatile("cp.async.commit_group;" ::: "memory"); }
__device__ __forceinline__ void cpa_wait0()  { asm volatile("cp.async.wait_group 0;" ::: "memory"); }

__device__ __forceinline__ void ldm4(uint32_t r[4], uint32_t addr) {
    asm volatile("ldmatrix.sync.aligned.m8n8.x4.shared.b16 {%0,%1,%2,%3}, [%4];"
                 : "=r"(r[0]), "=r"(r[1]), "=r"(r[2]), "=r"(r[3]) : "r"(addr));
}
__device__ __forceinline__ void mma_f16(float c[4], const uint32_t a[4],
                                        uint32_t b0, uint32_t b1) {
    asm volatile("mma.sync.aligned.m16n8k16.row.col.f32.f16.f16.f32 "
                 "{%0,%1,%2,%3}, {%4,%5,%6,%7}, {%8,%9}, {%0,%1,%2,%3};"
                 : "+f"(c[0]), "+f"(c[1]), "+f"(c[2]), "+f"(c[3])
                 : "r"(a[0]), "r"(a[1]), "r"(a[2]), "r"(a[3]), "r"(b0), "r"(b1));
}

__device__ __forceinline__ float sigmoidf_(float x) { return 1.f / (1.f + __expf(-x)); }

// ============================================================================
// Fused prep: blocks [0,1024) soft-threshold + compact the conv kernel
// (float4-vectorized scan); blocks [1024,3072) fp16-quantize W with a/g row
// interleave + bias pack.
// (On bench data lambda=0.1 is ~50 sigma -> nnz = 0; path kept for generality.)
// ============================================================================
__global__ void k_prep(const float* __restrict__ ker,
                       const float* __restrict__ W,
                       const float* __restrict__ bias) {
    if (blockIdx.x < H_) {
        __shared__ int cnt;
        int h = blockIdx.x;
        if (threadIdx.x == 0) cnt = 0;
        __syncthreads();
        const float4* kr4 = reinterpret_cast<const float4*>(ker + (size_t)h * N2L);
#pragma unroll
        for (int i4 = threadIdx.x; i4 < N2L / 4; i4 += 256) {
            float4 x4 = kr4[i4];
            float xs[4] = { x4.x, x4.y, x4.z, x4.w };
#pragma unroll
            for (int j = 0; j < 4; j++) {
                float x = xs[j];
                float a = fabsf(x) - LAM;
                if (a > 0.f) {
                    float s = (x > 0.f) ? a : -a;
                    int p = atomicAdd(&cnt, 1);
                    g_tpos[h * N2L + p] = i4 * 4 + j;
                    g_tval[h * N2L + p] = s;
                }
            }
        }
        __syncthreads();
        if (threadIdx.x == 0) g_nnz[h] = cnt;
    } else {
        int r = blockIdx.x - H_;                         // packed row 0..2047
        int orig = (r & 1) ? (H_ + (r >> 1)) : (r >> 1);
        const float4* wr4 = reinterpret_cast<const float4*>(W + (size_t)orig * KDIM);
        for (int k4 = threadIdx.x; k4 < KDIM / 4; k4 += 256) {
            float4 w4 = wr4[k4];
            __half2 lo = __floats2half2_rn(w4.x, w4.y);
            __half2 hi = __floats2half2_rn(w4.z, w4.w);
            uint32_t* dst = reinterpret_cast<uint32_t*>(g_wh + (size_t)r * KDIM + k4 * 4);
            dst[0] = *reinterpret_cast<uint32_t*>(&lo);
            dst[1] = *reinterpret_cast<uint32_t*>(&hi);
        }
        if (threadIdx.x == 0) g_bpack[r] = bias[orig];
    }
}

// ============================================================================
// Y-build: y[b,h,l] = silu(u*D[h] + sparse_conv) -> transpose -> fp16
// at y_t[(b*L+l)][h].  64x64 tile, smem transpose, uint4 coalesced stores.
// ============================================================================
__global__ void k_ybuild(const float* __restrict__ u, const float* __restrict__ D) {
    __shared__ __half sm[64][72];                  // 72-pad: 16B-aligned rows
    int b = blockIdx.z, h0 = blockIdx.y * 64, l0 = blockIdx.x * 64;
    int tx = threadIdx.x, ty = threadIdx.y;        // (32, 8)
    const float* ub = u + (size_t)b * H_ * L_;
#pragma unroll
    for (int rh = 0; rh < 8; rh++) {
        int hl = ty + rh * 8;
        int h = h0 + hl;
        const float* ur = ub + (size_t)h * L_;
        float d = D[h];
        int nn = g_nnz[h];
#pragma unroll
        for (int rl = 0; rl < 2; rl++) {
            int ll = rl * 32 + tx;
            int l = l0 + ll;
            float val = ur[l] * d;
            for (int tg = 0; tg < nn; tg++) {      // never taken on bench data
                int   p = g_tpos[h * N2L + tg];
                float v = g_tval[h * N2L + tg];
                int idx = (l - p) & (N2L - 1);
                if (idx < L_) val += v * ur[idx];
            }
            val = val * sigmoidf_(val);            // silu
            sm[ll][hl] = __float2half(val);
        }
    }
    __syncthreads();
    int t = ty * 32 + tx;
#pragma unroll
    for (int pass = 0; pass < 2; pass++) {
        int ll = pass * 32 + (t >> 3);
        int seg = t & 7;
        uint4 v = *reinterpret_cast<const uint4*>(&sm[ll][seg * 8]);
        *reinterpret_cast<uint4*>(g_yh + ((size_t)b * L_ + l0 + ll) * KDIM + h0 + seg * 8) = v;
    }
}

// ============================================================================
// GEMM: fp16 mma.sync (M=2048, N=16384, K=1024) + bias + GLU.
// CTA tile 64x128, 4 warps (2M x 2N), warp tile 32x64, KC=64, 2-stage
// cp.async, FOUR CTAs per SM (4 independent barrier domains), and ONE
// barrier per chunk: load(c+1) is issued after the top barrier, into the
// stage that barrier just proved free (all warps past compute(c-1)).
// ============================================================================
#define KC        64
#define NCHUNK    (KDIM / KC)                 // 16
#define A_SZ      8192                        // 64 rows x 128B
#define STG_SZ    24576                       // A 8KB | B 16KB
#define OFF_B     A_SZ
#define NSTG      2
#define SMEM_REQ  (NSTG * STG_SZ + 256)       // ~48.25KB -> 4 CTAs/SM (193KB)
#define NTHR      128

__device__ __forceinline__ void load_chunk(uint32_t stage, int m0, int n0, int c) {
    int tid = threadIdx.x;
    int k0 = c * KC;
#pragma unroll
    for (int j = 0; j < 4; j++) {              // A: 64 rows x 8 16B-segs = 512
        int idx = tid + j * NTHR;
        int row = idx >> 3, seg = idx & 7;
        cpa16(stage + SWZ(row * 128 + seg * 16),
              g_wh + (size_t)(m0 + row) * KDIM + k0 + seg * 8);
    }
#pragma unroll
    for (int j = 0; j < 8; j++) {              // B: 128 rows x 8 segs = 1024
        int idx = tid + j * NTHR;
        int row = idx >> 3, seg = idx & 7;
        cpa16(stage + OFF_B + SWZ(row * 128 + seg * 16),
              g_yh + (size_t)(n0 + row) * KDIM + k0 + seg * 8);
    }
}

__global__ void __launch_bounds__(NTHR, 4) k_gemm(float* __restrict__ out) {
    extern __shared__ char smem_raw[];
    uint32_t sb = (smem_u32(smem_raw) + 127u) & ~127u;
    int tid = threadIdx.x, wid = tid >> 5, lane = tid & 31;
    int warpM = wid & 1, warpN = wid >> 1;     // 2M x 2N warps, warp tile 32x64

    int m0 = blockIdx.y * 64;
    int n0 = blockIdx.x * 128;

    float acc[2][8][4];
#pragma unroll
    for (int i = 0; i < 2; i++)
#pragma unroll
        for (int j = 0; j < 8; j++)
#pragma unroll
            for (int k = 0; k < 4; k++) acc[i][j][k] = 0.f;

    // per-lane ldmatrix addressing (pre-swizzled row bases)
    int rA = warpM * 32 + (lane & 15);
    uint32_t aRow0 = (uint32_t)(rA * 128),        aXor0 = (uint32_t)((rA & 7) << 4);
    uint32_t aRow1 = (uint32_t)((rA + 16) * 128), aXor1 = (uint32_t)(((rA + 16) & 7) << 4);
    uint32_t aHalf = ((lane >> 4) & 1) * 16;
    int rB = warpN * 64 + (lane & 7) + (((lane >> 4) & 1) << 3);
    uint32_t bHalf = ((lane >> 3) & 1) * 16;
    uint32_t bRow[4], bXor[4];
#pragma unroll
    for (int nf = 0; nf < 4; nf++) {
        int rr = rB + nf * 16;
        bRow[nf] = (uint32_t)(rr * 128);
        bXor[nf] = (uint32_t)((rr & 7) << 4);
    }

    // prologue: chunk 0 in flight
    load_chunk(sb + 0 * STG_SZ, m0, n0, 0);
    cpa_commit();

    for (int c = 0; c < NCHUNK; c++) {
        cpa_wait0();                           // chunk c landed (only group pending)
        // Single barrier per chunk:
        //  (a) chunk c visible to all warps;
        //  (b) all warps are past compute(c-1) (program order), so stage
        //      (c+1)&1 == (c-1)&1 is free for the load issued below.
        __syncthreads();
        if (c + 1 < NCHUNK) {
            load_chunk(sb + ((c + 1) & 1) * STG_SZ, m0, n0, c + 1);
            cpa_commit();                      // runs async under compute(c)
        }

        uint32_t stage = sb + (c & 1) * STG_SZ;
#pragma unroll
        for (int ks = 0; ks < 4; ks++) {
            uint32_t xa = (uint32_t)(ks * 32) + aHalf;
            uint32_t xb = (uint32_t)(ks * 32) + bHalf;
            uint32_t af0[4], af1[4], bf[4][4];
            ldm4(af0, stage + aRow0 + (xa ^ aXor0));
            ldm4(af1, stage + aRow1 + (xa ^ aXor1));
#pragma unroll
            for (int nf = 0; nf < 4; nf++)
                ldm4(bf[nf], stage + OFF_B + bRow[nf] + (xb ^ bXor[nf]));
#pragma unroll
            for (int nf = 0; nf < 4; nf++) {
                mma_f16(acc[0][nf * 2 + 0], af0, bf[nf][0], bf[nf][1]);
                mma_f16(acc[0][nf * 2 + 1], af0, bf[nf][2], bf[nf][3]);
                mma_f16(acc[1][nf * 2 + 0], af1, bf[nf][0], bf[nf][1]);
                mma_f16(acc[1][nf * 2 + 1], af1, bf[nf][2], bf[nf][3]);
            }
        }
    }

    // ---------------- epilogue: bias + GLU (a*sigmoid(g)) ----------------
    // Even lanes hold 'a' rows; float2 stores are full 32B sectors (efficient).
    int g = lane >> 2, q = lane & 3;
    int b = n0 >> 12;                               // n0 / 4096 (128 | 4096)
    int lcol = (n0 & (L_ - 1)) + warpN * 64 + q * 2;
    bool isA = ((g & 1) == 0);                      // even packed row -> 'a'
#pragma unroll
    for (int mf = 0; mf < 2; mf++) {
        int row0 = warpM * 32 + mf * 16 + g;        // rows for regs 0,1
        int row1 = row0 + 8;                        // rows for regs 2,3
        float bias0 = g_bpack[m0 + row0];
        float bias1 = g_bpack[m0 + row1];
        int h0 = (m0 + row0) >> 1;
        int h1 = (m0 + row1) >> 1;
        float* o0 = out + ((size_t)b * H_ + h0) * L_ + lcol;
        float* o1 = out + ((size_t)b * H_ + h1) * L_ + lcol;
#pragma unroll
        for (int nf = 0; nf < 8; nf++) {
            float v0 = acc[mf][nf][0] + bias0;
            float v1 = acc[mf][nf][1] + bias0;
            float v2 = acc[mf][nf][2] + bias1;
            float v3 = acc[mf][nf][3] + bias1;
            float p0 = __shfl_xor_sync(0xffffffffu, v0, 4);
            float p1 = __shfl_xor_sync(0xffffffffu, v1, 4);
            float p2 = __shfl_xor_sync(0xffffffffu, v2, 4);
            float p3 = __shfl_xor_sync(0xffffffffu, v3, 4);
            if (isA) {
                float2 r0 = make_float2(v0 * sigmoidf_(p0), v1 * sigmoidf_(p1));
                float2 r1 = make_float2(v2 * sigmoidf_(p2), v3 * sigmoidf_(p3));
                *reinterpret_cast<float2*>(o0 + nf * 8) = r0;
                *reinterpret_cast<float2*>(o1 + nf * 8) = r1;
            }
        }
    }
}

// ============================================================================
// launcher
// ============================================================================
extern "C" void kernel_launch(void* const* d_in, const int* in_sizes, int n_in,
                              void* d_out, int out_size) {
    const float* u    = (const float*)d_in[0];   // (B,H,L)
    const float* ker  = (const float*)d_in[1];   // (1,H,2L)
    const float* D    = (const float*)d_in[2];   // (1,H)
    const float* W    = (const float*)d_in[3];   // (2H, H)
    const float* bias = (const float*)d_in[4];   // (2H,)
    float* out = (float*)d_out;                  // (B,H,L)

    k_prep<<<H_ + MDIM, 256>>>(ker, W, bias);
    k_ybuild<<<dim3(L_ / 64, H_ / 64, B_), dim3(32, 8)>>>(u, D);

    cudaFuncSetAttribute(k_gemm, cudaFuncAttributeMaxDynamicSharedMemorySize, SMEM_REQ);
    k_gemm<<<dim3(NBL / 128, MDIM / 64), NTHR, SMEM_REQ>>>(out);
}